// round 4
// baseline (speedup 1.0000x reference)
#include <cuda_runtime.h>
#include <math.h>

#define SQ   512
#define BB   64
#define FIN  512
#define HH   512
#define G4   2048   // 4*H

#define NLOOP   148              // gemm looper blocks
#define NPERS   128              // persistent recurrence blocks
#define NTILES  4096             // 256 m-tiles x 16 n-tiles
#define MT_CNT  256              // m-tiles (2 timesteps each)

typedef unsigned long long ull;

// Scratch (static device arrays: allocation-guard safe)
__device__ float g_xg[(long long)SQ * BB * G4];   // input-projection gates [S, B, 4H]
__device__ float g_c [(long long)SQ * BB * HH];   // fallback c-state history
__device__ int   g_bar[SQ];                       // per-step h-ready counters
__device__ int   g_xflag[MT_CNT];                 // per-m-tile xg-ready counters (target 16)

__device__ __forceinline__ float sig(float x) { return 1.0f / (1.0f + expf(-x)); }

__device__ __forceinline__ void ffma2(ull& d, ull a, ull b) {
    asm("fma.rn.f32x2 %0, %1, %2, %0;" : "+l"(d) : "l"(a), "l"(b));
}
__device__ __forceinline__ ull packf2(float x, float y) {
    ull d; asm("mov.b64 %0, {%1, %2};" : "=l"(d) : "f"(x), "f"(y)); return d;
}
__device__ __forceinline__ float2 unpackf2(ull v) {
    float2 r; asm("mov.b64 {%0, %1}, %2;" : "=f"(r.x), "=f"(r.y) : "l"(v)); return r;
}
__device__ __forceinline__ int ld_acq(const int* p) {
    int v; asm volatile("ld.acquire.gpu.global.s32 %0, [%1];" : "=r"(v) : "l"(p) : "memory");
    return v;
}

// ---------------------------------------------------------------------------
// bar_init: zero all flags (runs every graph replay, before the fused kernel)
// ---------------------------------------------------------------------------
__global__ void bar_init() {
    g_bar[threadIdx.x] = 0;
    if (threadIdx.x < MT_CNT) g_xflag[threadIdx.x] = 0;
}

// ---------------------------------------------------------------------------
// Shared-memory layout (uniform dynamic smem, 2 blocks/SM REQUIRED):
//  looper blocks use the first 8.5KB as As/Bs.
//  persistent blocks: sW = 16 w_hh rows, 516-stride + per-nn 8-word skew
//                     sH = 64 x 260 (one K-half of h), overlaid by reduce buf.
// ---------------------------------------------------------------------------
#define SW_NNSKEW  2072          // nn group base stride in floats (4*516 + 8)
#define SW_FLOATS  (16 * 516 + 32)
#define SH_STRIDE  260
#define SH_FLOATS  (64 * SH_STRIDE)
#define RED_S      36
#define SMEM_FLOATS (SW_FLOATS + SH_FLOATS)      // 24928
#define SMEM_BYTES  (SMEM_FLOATS * 4)            // 99712

// ---------------------------------------------------------------------------
// GEMM looper body: blocks 0..147, each loops tiles bid, bid+148, ...
// tile = m_tile*16 + n_tile; after each tile, bump g_xflag[m_tile].
// ---------------------------------------------------------------------------
__device__ void gemm_worker(float* sm,
                            const float* __restrict__ A, const float* __restrict__ W,
                            const float* __restrict__ bih, const float* __restrict__ bhh,
                            float* __restrict__ C, int bid)
{
    float (*As)[132] = (float(*)[132])sm;
    float (*Bs)[132] = (float(*)[132])(sm + 8 * 132);

    const int tid  = threadIdx.x;
    const int tx   = tid & 15;
    const int ty   = tid >> 4;
    const int lrow = tid >> 1;
    const int lk4  = (tid & 1) * 4;

    for (int tile = bid; tile < NTILES; tile += NLOOP) {
        const int mt = tile >> 4;
        const int m0 = mt * 128;
        const int n0 = (tile & 15) * 128;

        const float* Aptr = A + (size_t)(m0 + lrow) * FIN + lk4;
        const float* Wptr = W + (size_t)(n0 + lrow) * FIN + lk4;

        ull acc2[4][8];
        #pragma unroll
        for (int i = 0; i < 4; i++)
            #pragma unroll
            for (int j = 0; j < 8; j++) acc2[i][j] = 0ULL;

        float4 ra = *(const float4*)(Aptr);
        float4 rb = *(const float4*)(Wptr);

        for (int kb = 0; kb < 64; kb++) {
            As[lk4 + 0][lrow] = ra.x; As[lk4 + 1][lrow] = ra.y;
            As[lk4 + 2][lrow] = ra.z; As[lk4 + 3][lrow] = ra.w;
            Bs[lk4 + 0][lrow] = rb.x; Bs[lk4 + 1][lrow] = rb.y;
            Bs[lk4 + 2][lrow] = rb.z; Bs[lk4 + 3][lrow] = rb.w;
            __syncthreads();

            if (kb < 63) {
                ra = *(const float4*)(Aptr + (kb + 1) * 8);
                rb = *(const float4*)(Wptr + (kb + 1) * 8);
            }

            #pragma unroll
            for (int kk = 0; kk < 8; kk++) {
                ulonglong2 a01 = *(const ulonglong2*)&As[kk][ty * 8];
                ulonglong2 a23 = *(const ulonglong2*)&As[kk][ty * 8 + 4];
                ull av[4] = {a01.x, a01.y, a23.x, a23.y};
                float4 b0 = *(const float4*)&Bs[kk][tx * 8];
                float4 b1 = *(const float4*)&Bs[kk][tx * 8 + 4];
                ull rbk[8];
                rbk[0] = packf2(b0.x, b0.x); rbk[1] = packf2(b0.y, b0.y);
                rbk[2] = packf2(b0.z, b0.z); rbk[3] = packf2(b0.w, b0.w);
                rbk[4] = packf2(b1.x, b1.x); rbk[5] = packf2(b1.y, b1.y);
                rbk[6] = packf2(b1.z, b1.z); rbk[7] = packf2(b1.w, b1.w);
                #pragma unroll
                for (int i2 = 0; i2 < 4; i2++)
                    #pragma unroll
                    for (int j = 0; j < 8; j++)
                        ffma2(acc2[i2][j], av[i2], rbk[j]);
            }
            __syncthreads();
        }

        float bias[8];
        #pragma unroll
        for (int j = 0; j < 8; j++) {
            int n = n0 + tx * 8 + j;
            bias[j] = bih[n] + bhh[n];
        }
        #pragma unroll
        for (int i2 = 0; i2 < 4; i2++) {
            float r0[8], r1[8];
            #pragma unroll
            for (int j = 0; j < 8; j++) {
                float2 v = unpackf2(acc2[i2][j]);
                r0[j] = v.x + bias[j];
                r1[j] = v.y + bias[j];
            }
            int m = m0 + ty * 8 + 2 * i2;
            float* p0 = C + (size_t)m * G4 + n0 + tx * 8;
            float* p1 = p0 + G4;
            *(float4*)(p0)     = make_float4(r0[0], r0[1], r0[2], r0[3]);
            *(float4*)(p0 + 4) = make_float4(r0[4], r0[5], r0[6], r0[7]);
            *(float4*)(p1)     = make_float4(r1[0], r1[1], r1[2], r1[3]);
            *(float4*)(p1 + 4) = make_float4(r1[4], r1[5], r1[6], r1[7]);
        }

        // Publish this tile
        __threadfence();
        __syncthreads();
        if (tid == 0) atomicAdd(&g_xflag[mt], 1);
        __syncthreads();
    }
}

// ---------------------------------------------------------------------------
// Persistent recurrence body: 128 blocks, pbid owns 4 h-columns n0 = 4*pbid.
// tid = ks(3b)<<5 | bg(3b)<<2 | nn(2b). Thread tile: 8 batches x 4 gates.
// h staged in two K-halves of 256 (sH 64x260). c-state lives in a register.
// ---------------------------------------------------------------------------
__device__ void lstm_worker(float* sm,
                            const float* __restrict__ xg,
                            const float* __restrict__ Whh,
                            float* __restrict__ hout,
                            float* __restrict__ cout,
                            int pbid)
{
    float* sW  = sm;                  // 16*516 + 32 (skewed rows, persistent)
    float* sH  = sm + SW_FLOATS;      // 64 x 260, one K-half
    float* red = sH;                  // reduce buffer overlays sH (256 x 36)

    const int tid = threadIdx.x;
    const int ks  = tid >> 5;
    const int bg  = (tid >> 2) & 7;
    const int nn  = tid & 3;
    const int n0  = pbid * 4;

    // Stage the 16 w_hh rows once (full K=512). Dest row r = nn*4+g with skew.
    #pragma unroll
    for (int i = 0; i < 8; i++) {
        int s  = tid + 256 * i;            // 0..2047 float4 units
        int r  = s >> 7;
        int k4 = (s & 127) * 4;
        int g  = r & 3;
        int nr = r >> 2;
        float4 v = *(const float4*)(Whh + (size_t)(g * HH + n0 + nr) * HH + k4);
        float* d = sW + nr * SW_NNSKEW + g * 516 + k4;
        d[0] = v.x; d[1] = v.y; d[2] = v.z; d[3] = v.w;
    }
    __syncthreads();

    const int ob = tid >> 2;            // batch 0..63 (output coordinate)
    const int on = n0 + (tid & 3);      // h column
    float creg = 0.0f;

    const float* wbase = sW + nn * SW_NNSKEW;
    const float* hb    = sH + bg * SH_STRIDE + ks * 32;

    for (int t = 0; t < SQ; t++) {
        // Wait for xg[t] (looper flags) and h(t-1)
        if (tid == 0) {
            while (ld_acq(&g_xflag[t >> 1]) < 16) {}
            if (t > 0) { while (ld_acq(&g_bar[t - 1]) < 128) {} }
        }
        __syncthreads();

        float s0 = 0.f, s1 = 0.f, s2 = 0.f, s3 = 0.f;

        if (t > 0) {
            ull acc[8][4];
            #pragma unroll
            for (int bb = 0; bb < 8; bb++)
                #pragma unroll
                for (int g = 0; g < 4; g++) acc[bb][g] = 0ULL;

            const float* hp = hout + (size_t)(t - 1) * BB * HH;

            #pragma unroll
            for (int half = 0; half < 2; half++) {
                // Stage h K-half: 64 x 256 floats
                const float* hsrc = hp + half * 256;
                #pragma unroll
                for (int i = 0; i < 16; i++) {
                    int s  = tid + 256 * i;        // 0..4095 float4 units
                    int b  = s >> 6;
                    int k4 = (s & 63) * 4;
                    float4 v = *(const float4*)(hsrc + b * HH + k4);
                    float* d = sH + b * SH_STRIDE + k4;
                    d[0] = v.x; d[1] = v.y; d[2] = v.z; d[3] = v.w;
                }
                __syncthreads();

                const float* wr = wbase + half * 256 + ks * 32;
                #pragma unroll
                for (int k = 0; k < 32; k += 4) {
                    ulonglong2 w0 = *(const ulonglong2*)(wr + k);
                    ulonglong2 w1 = *(const ulonglong2*)(wr + 516 + k);
                    ulonglong2 w2 = *(const ulonglong2*)(wr + 1032 + k);
                    ulonglong2 w3 = *(const ulonglong2*)(wr + 1548 + k);
                    #pragma unroll
                    for (int bb = 0; bb < 8; bb++) {
                        ulonglong2 h = *(const ulonglong2*)(hb + bb * 2080 + k);
                        ffma2(acc[bb][0], h.x, w0.x); ffma2(acc[bb][0], h.y, w0.y);
                        ffma2(acc[bb][1], h.x, w1.x); ffma2(acc[bb][1], h.y, w1.y);
                        ffma2(acc[bb][2], h.x, w2.x); ffma2(acc[bb][2], h.y, w2.y);
                        ffma2(acc[bb][3], h.x, w3.x); ffma2(acc[bb][3], h.y, w3.y);
                    }
                }
                __syncthreads();   // done reading this half before sH reuse
            }

            // Partials -> red (overlays sH): red[tid][bb] = gates float4
            float4* rp = (float4*)(red + tid * RED_S);
            #pragma unroll
            for (int bb = 0; bb < 8; bb++) {
                float2 a0 = unpackf2(acc[bb][0]);
                float2 a1 = unpackf2(acc[bb][1]);
                float2 a2 = unpackf2(acc[bb][2]);
                float2 a3 = unpackf2(acc[bb][3]);
                rp[bb] = make_float4(a0.x + a0.y, a1.x + a1.y,
                                     a2.x + a2.y, a3.x + a3.y);
            }
            __syncthreads();

            // Reduce across the 8 K-chunks for this thread's (ob, on)
            const int lane32 = tid & 31;
            const int bbl = ob >> 3;
            #pragma unroll
            for (int p = 0; p < 8; p++) {
                float4 v = *(const float4*)(red + (p * 32 + lane32) * RED_S + bbl * 4);
                s0 += v.x; s1 += v.y; s2 += v.z; s3 += v.w;
            }
        }

        // Gate epilogue + state update (gate order: i, f, g, o)
        const float* xgt = xg + (size_t)t * BB * G4 + (size_t)ob * G4 + on;
        float pi = xgt[0]    + s0;
        float pf = xgt[512]  + s1;
        float pg = xgt[1024] + s2;
        float po = xgt[1536] + s3;
        float cn = sig(pf) * creg + sig(pi) * tanhf(pg);
        float hn = sig(po) * tanhf(cn);
        creg = cn;
        hout[(size_t)t * BB * HH + ob * HH + on] = hn;
        cout[(size_t)t * BB * HH + ob * HH + on] = cn;

        // Publish step t
        __threadfence();
        __syncthreads();
        if (tid == 0) atomicAdd(&g_bar[t], 1);
    }
}

// ---------------------------------------------------------------------------
// Fused kernel: blocks 0..147 = gemm loopers, 148..275 = persistent recurrence.
// 2 blocks/SM co-residency (99.7KB smem each) => all 276 resident in wave 1.
// ---------------------------------------------------------------------------
__global__ __launch_bounds__(256, 2)
void fused(const float* __restrict__ seq, const float* __restrict__ wih,
           const float* __restrict__ whh, const float* __restrict__ bih,
           const float* __restrict__ bhh,
           float* __restrict__ xg, float* __restrict__ hout, float* __restrict__ cout)
{
    extern __shared__ float sm[];
    const int bid = blockIdx.x;
    if (bid < NLOOP) {
        gemm_worker(sm, seq, wih, bih, bhh, xg, bid);
    } else {
        lstm_worker(sm, xg, whh, hout, cout, bid - NLOOP);
    }
}

// ---------------------------------------------------------------------------
// Host
// ---------------------------------------------------------------------------
extern "C" void kernel_launch(void* const* d_in, const int* in_sizes, int n_in,
                              void* d_out, int out_size)
{
    const float* seq = (const float*)d_in[0];
    const float* wih = (const float*)d_in[1];
    const float* whh = (const float*)d_in[2];
    const float* bih = (const float*)d_in[3];
    const float* bhh = (const float*)d_in[4];
    float* out = (float*)d_out;

    float *xg, *cscr;
    cudaGetSymbolAddress((void**)&xg, g_xg);
    cudaGetSymbolAddress((void**)&cscr, g_c);

    const size_t SBH = (size_t)SQ * BB * HH;
    float* cbase = ((size_t)out_size >= 2 * SBH) ? (out + SBH) : cscr;

    bar_init<<<1, SQ>>>();

    cudaFuncSetAttribute(fused, cudaFuncAttributeMaxDynamicSharedMemorySize,
                         SMEM_BYTES);
    fused<<<NLOOP + NPERS, 256, SMEM_BYTES>>>(seq, wih, whh, bih, bhh,
                                              xg, out, cbase);
}